// round 2
// baseline (speedup 1.0000x reference)
#include <cuda_runtime.h>
#include <cuda_bf16.h>
#include <float.h>

// Problem constants (fixed by the dataset)
#define MAX_NODES 100000
#define D_FEAT 32
#define D_HID 64
#define D_OUT 64

// Scratch: per-node precomputed terms.
// U[j] = x_j @ W1[:32] + pos_j @ W1[32:35] + b1   (N x 64)
// P[i] = pos_i @ W1[32:35]                        (N x 64)
// Per-edge preactivation = U[src] - P[dst].
__device__ float g_U[MAX_NODES * D_HID];
__device__ float g_P[MAX_NODES * D_HID];

// 1 if edge_index is genuinely int64, 0 if it is int32 on disk
// (JAX silently downgrades int64 -> int32 when x64 is disabled).
__device__ int g_is64;

// ---------------------------------------------------------------------------
// Kernel 0: detect edge_index element width. Sample entries interpreted as
// int64; real int64 node ids are all in [0, n). int32 data read as int64
// packs two edges per word -> values out of range with ~certainty over 4K
// samples. Single block, deterministic.
// ---------------------------------------------------------------------------
__global__ void detect_kernel(const long long* __restrict__ ei64, int E, int n) {
    __shared__ int bad;
    if (threadIdx.x == 0) bad = 0;
    __syncthreads();
    // Reading i < min(4096, E) int64 words touches <= 8*4096 bytes, which is
    // within the buffer even if it is int32 (2*E*4 = 8E bytes, E = 1.6M).
    int samples = min(4096, E);
    for (int i = threadIdx.x; i < samples; i += blockDim.x) {
        long long v = ei64[i];
        if (v < 0 || v >= (long long)n) atomicOr(&bad, 1);
    }
    __syncthreads();
    if (threadIdx.x == 0) g_is64 = bad ? 0 : 1;
}

// ---------------------------------------------------------------------------
// Kernel 1: per-node precompute of U and P. One thread per (node, hid).
// ---------------------------------------------------------------------------
__global__ void precompute_kernel(const float* __restrict__ x,
                                  const float* __restrict__ pos,
                                  const float* __restrict__ W1,
                                  const float* __restrict__ b1,
                                  int n) {
    __shared__ float W1s[35 * 64];
    __shared__ float b1s[64];
    for (int i = threadIdx.x; i < 35 * 64; i += blockDim.x) W1s[i] = W1[i];
    if (threadIdx.x < 64) b1s[threadIdx.x] = b1[threadIdx.x];
    __syncthreads();

    int gid = blockIdx.x * blockDim.x + threadIdx.x;
    int node = gid >> 6;
    int k = gid & 63;
    if (node >= n) return;

    const float* xr = x + node * D_FEAT;
    float acc = b1s[k];
#pragma unroll
    for (int f = 0; f < D_FEAT; f++) {
        acc = fmaf(xr[f], W1s[f * 64 + k], acc);
    }
    float px = pos[node * 3 + 0];
    float py = pos[node * 3 + 1];
    float pz = pos[node * 3 + 2];
    float pp = px * W1s[32 * 64 + k];
    pp = fmaf(py, W1s[33 * 64 + k], pp);
    pp = fmaf(pz, W1s[34 * 64 + k], pp);

    g_U[node * 64 + k] = acc + pp;
    g_P[node * 64 + k] = pp;
}

// ---------------------------------------------------------------------------
// Kernel 2: init output to -FLT_MAX (every node has a self-loop, so every
// element gets at least one real candidate).
// ---------------------------------------------------------------------------
__global__ void init_out_kernel(float* __restrict__ out, int total) {
    int i = blockIdx.x * blockDim.x + threadIdx.x;
    if (i < total) out[i] = -FLT_MAX;
}

// ---------------------------------------------------------------------------
// float atomicMax via int/uint bit tricks (IEEE total order for finite floats)
// ---------------------------------------------------------------------------
__device__ __forceinline__ void atomicMaxF(float* addr, float v) {
    if (v >= 0.0f) {
        atomicMax((int*)addr, __float_as_int(v));
    } else {
        atomicMin((unsigned int*)addr, __float_as_uint(v));
    }
}

// ---------------------------------------------------------------------------
// Kernel 3: edge kernel. Edges e in [0, E) are real edges; e in [E, E+n) are
// self loops (src = dst = e - E). One warp processes 2 edges at a time so the
// shared-memory W2 reads are amortized across both.
// Thread `lane` computes output channels k = lane and k = lane + 32.
// h1 (64 values) lives distributed across the warp (2 regs/lane), broadcast
// per k-step via shfl.
// ---------------------------------------------------------------------------
__global__ void __launch_bounds__(256) edge_kernel(
    const void* __restrict__ ei_raw,    // [2, E] int64 OR int32: row0 src, row1 dst
    const float* __restrict__ W2,       // [64, 64]
    const float* __restrict__ b2,       // [64]
    float* __restrict__ out,            // [n, 64]
    int n, int E) {
    __shared__ float W2s[64 * 64];
    __shared__ float b2s[64];
    for (int i = threadIdx.x; i < 64 * 64; i += blockDim.x) W2s[i] = W2[i];
    if (threadIdx.x < 64) b2s[threadIdx.x] = b2[threadIdx.x];
    __syncthreads();

    const int is64 = g_is64;
    const long long* ei64 = (const long long*)ei_raw;
    const int*       ei32 = (const int*)ei_raw;

    const int lane = threadIdx.x & 31;
    const int warpsPerBlock = blockDim.x >> 5;
    const int warpId = blockIdx.x * warpsPerBlock + (threadIdx.x >> 5);
    const int nWarps = gridDim.x * warpsPerBlock;
    const int total = E + n;

    const float blo = b2s[lane];
    const float bhi = b2s[lane + 32];

    for (int base = warpId * 2; base < total; base += nWarps * 2) {
        int e0 = base;
        int e1 = base + 1;
        bool v1 = (e1 < total);

        long long s0, d0, s1 = 0, d1 = 0;
        if (e0 < E) {
            if (is64) { s0 = ei64[e0]; d0 = ei64[E + e0]; }
            else      { s0 = ei32[e0]; d0 = ei32[E + e0]; }
        } else { s0 = e0 - E; d0 = s0; }
        if (v1) {
            if (e1 < E) {
                if (is64) { s1 = ei64[e1]; d1 = ei64[E + e1]; }
                else      { s1 = ei32[e1]; d1 = ei32[E + e1]; }
            } else { s1 = e1 - E; d1 = s1; }
        }

        // h1 for both edges, distributed: h?0 = h[lane], h?1 = h[lane+32]
        const float* Us0 = g_U + s0 * 64;
        const float* Pd0 = g_P + d0 * 64;
        float h00 = fmaxf(Us0[lane]      - Pd0[lane],      0.0f);
        float h01 = fmaxf(Us0[lane + 32] - Pd0[lane + 32], 0.0f);
        float h10 = 0.0f, h11 = 0.0f;
        if (v1) {
            const float* Us1 = g_U + s1 * 64;
            const float* Pd1 = g_P + d1 * 64;
            h10 = fmaxf(Us1[lane]      - Pd1[lane],      0.0f);
            h11 = fmaxf(Us1[lane + 32] - Pd1[lane + 32], 0.0f);
        }

        float a00 = 0.0f, a01 = 0.0f;  // edge0: k=lane, k=lane+32
        float a10 = 0.0f, a11 = 0.0f;  // edge1
#pragma unroll
        for (int m = 0; m < 32; m++) {
            float wa = W2s[m * 64 + lane];
            float wb = W2s[m * 64 + 32 + lane];
            float wc = W2s[(m + 32) * 64 + lane];
            float wd = W2s[(m + 32) * 64 + 32 + lane];
            float x0 = __shfl_sync(0xffffffffu, h00, m);  // h_e0[m]
            float y0 = __shfl_sync(0xffffffffu, h01, m);  // h_e0[m+32]
            float x1 = __shfl_sync(0xffffffffu, h10, m);
            float y1 = __shfl_sync(0xffffffffu, h11, m);
            a00 = fmaf(x0, wa, a00); a00 = fmaf(y0, wc, a00);
            a01 = fmaf(x0, wb, a01); a01 = fmaf(y0, wd, a01);
            a10 = fmaf(x1, wa, a10); a10 = fmaf(y1, wc, a10);
            a11 = fmaf(x1, wb, a11); a11 = fmaf(y1, wd, a11);
        }
        a00 += blo; a01 += bhi;
        a10 += blo; a11 += bhi;

        // Scatter-max with cheap pre-check. out[] is monotone non-decreasing,
        // so a stale read only causes a redundant atomic, never a missed one.
        {
            float* o = out + d0 * 64;
            if (a00 > o[lane])      atomicMaxF(o + lane, a00);
            if (a01 > o[lane + 32]) atomicMaxF(o + lane + 32, a01);
        }
        if (v1) {
            float* o = out + d1 * 64;
            if (a10 > o[lane])      atomicMaxF(o + lane, a10);
            if (a11 > o[lane + 32]) atomicMaxF(o + lane + 32, a11);
        }
    }
}

// ---------------------------------------------------------------------------
// Launch
// ---------------------------------------------------------------------------
extern "C" void kernel_launch(void* const* d_in, const int* in_sizes, int n_in,
                              void* d_out, int out_size) {
    const float* x   = (const float*)d_in[0];    // [n, 32]
    const float* pos = (const float*)d_in[1];    // [n, 3]
    const void*  ei  = d_in[2];                  // [2, E] int64 or int32
    const float* W1  = (const float*)d_in[3];    // [35, 64]
    const float* b1  = (const float*)d_in[4];    // [64]
    const float* W2  = (const float*)d_in[5];    // [64, 64]
    const float* b2  = (const float*)d_in[6];    // [64]
    float*       out = (float*)d_out;            // [n, 64]

    int n = in_sizes[0] / D_FEAT;
    int E = in_sizes[2] / 2;

    // 0) detect edge_index dtype (int64 vs int32)
    detect_kernel<<<1, 256>>>((const long long*)ei, E, n);

    // 1) per-node precompute
    {
        int threads = 256;
        int blocks = (n * 64 + threads - 1) / threads;
        precompute_kernel<<<blocks, threads>>>(x, pos, W1, b1, n);
    }
    // 2) init output
    {
        int threads = 256;
        int blocks = (n * 64 + threads - 1) / threads;
        init_out_kernel<<<blocks, threads>>>(out, n * 64);
    }
    // 3) edge kernel: one warp per 2 edges
    {
        int total = E + n;
        int pairs = (total + 1) / 2;
        int warpsPerBlock = 8;  // 256 threads
        int blocks = (pairs + warpsPerBlock - 1) / warpsPerBlock;
        edge_kernel<<<blocks, 256>>>(ei, W2, b2, out, n, E);
    }
}

// round 3
// speedup vs baseline: 1.2892x; 1.2892x over previous
#include <cuda_runtime.h>
#include <cuda_bf16.h>
#include <float.h>

// Problem constants (fixed by the dataset)
#define MAX_NODES 100000
#define D_FEAT 32
#define D_HID 64
#define D_OUT 64
#define TILE_E 128
#define H_STRIDE 68   // floats per H row (64 + pad, 16B-aligned)

// Scratch: per-node precomputed terms.
// U[j] = x_j @ W1[:32] + pos_j @ W1[32:35] + b1   (N x 64)
// P[i] = pos_i @ W1[32:35]                        (N x 64)
// Per-edge preactivation = U[src] - P[dst].
__device__ float g_U[MAX_NODES * D_HID];
__device__ float g_P[MAX_NODES * D_HID];

// 1 if edge_index is genuinely int64, 0 if int32 on disk.
__device__ int g_is64;

// ---------------------------------------------------------------------------
// packed fp32x2 helpers (sm_100+ PTX; bit-exact pair of fp32 FMAs)
// ---------------------------------------------------------------------------
__device__ __forceinline__ void ffma2(unsigned long long& d,
                                      unsigned long long a,
                                      unsigned long long b) {
    asm("fma.rn.f32x2 %0, %1, %2, %0;" : "+l"(d) : "l"(a), "l"(b));
}
__device__ __forceinline__ unsigned long long packdup(float x) {
    unsigned long long r;
    asm("mov.b64 %0, {%1, %1};" : "=l"(r) : "f"(x));
    return r;
}
__device__ __forceinline__ void unpack2(unsigned long long v, float& lo, float& hi) {
    asm("mov.b64 {%0, %1}, %2;" : "=f"(lo), "=f"(hi) : "l"(v));
}

// ---------------------------------------------------------------------------
// Kernel 0: detect edge_index element width (int64 vs int32).
// ---------------------------------------------------------------------------
__global__ void detect_kernel(const long long* __restrict__ ei64, int E, int n) {
    __shared__ int bad;
    if (threadIdx.x == 0) bad = 0;
    __syncthreads();
    int samples = min(4096, E);
    for (int i = threadIdx.x; i < samples; i += blockDim.x) {
        long long v = ei64[i];
        if (v < 0 || v >= (long long)n) atomicOr(&bad, 1);
    }
    __syncthreads();
    if (threadIdx.x == 0) g_is64 = bad ? 0 : 1;
}

// ---------------------------------------------------------------------------
// Kernel 1: per-node precompute of U and P. One thread per (node, hid).
// ---------------------------------------------------------------------------
__global__ void precompute_kernel(const float* __restrict__ x,
                                  const float* __restrict__ pos,
                                  const float* __restrict__ W1,
                                  const float* __restrict__ b1,
                                  int n) {
    __shared__ float W1s[35 * 64];
    __shared__ float b1s[64];
    for (int i = threadIdx.x; i < 35 * 64; i += blockDim.x) W1s[i] = W1[i];
    if (threadIdx.x < 64) b1s[threadIdx.x] = b1[threadIdx.x];
    __syncthreads();

    int gid = blockIdx.x * blockDim.x + threadIdx.x;
    int node = gid >> 6;
    int k = gid & 63;
    if (node >= n) return;

    const float* xr = x + node * D_FEAT;
    float acc = b1s[k];
#pragma unroll
    for (int f = 0; f < D_FEAT; f++) {
        acc = fmaf(xr[f], W1s[f * 64 + k], acc);
    }
    float px = pos[node * 3 + 0];
    float py = pos[node * 3 + 1];
    float pz = pos[node * 3 + 2];
    float pp = px * W1s[32 * 64 + k];
    pp = fmaf(py, W1s[33 * 64 + k], pp);
    pp = fmaf(pz, W1s[34 * 64 + k], pp);

    g_U[node * 64 + k] = acc + pp;
    g_P[node * 64 + k] = pp;
}

// ---------------------------------------------------------------------------
// Kernel 2: init output to -FLT_MAX.
// ---------------------------------------------------------------------------
__global__ void init_out_kernel(float* __restrict__ out, int total) {
    int i = blockIdx.x * blockDim.x + threadIdx.x;
    if (i < total) out[i] = -FLT_MAX;
}

// ---------------------------------------------------------------------------
// float atomicMax via int/uint bit tricks
// ---------------------------------------------------------------------------
__device__ __forceinline__ void atomicMaxF(float* addr, float v) {
    if (v >= 0.0f) {
        atomicMax((int*)addr, __float_as_int(v));
    } else {
        atomicMin((unsigned int*)addr, __float_as_uint(v));
    }
}

// ---------------------------------------------------------------------------
// Kernel 3: edge kernel, register-tiled.
// Tile = 128 edges x 64 outputs per block (256 threads).
// Stage 1: gather + relu into smem H tile.
// Stage 2: GEMM, thread tile 8 edges x 4 outputs (2 f32x2 pairs), m unroll 4.
// Stage 3: scatter-max with pre-check.
// Thread map: eg = tid & 15 (edge group; edges eg, eg+16, ..., eg+112),
//             kb = (tid >> 4) * 4 (output columns kb..kb+3).
// ---------------------------------------------------------------------------
__global__ void __launch_bounds__(256, 2) edge_kernel(
    const void* __restrict__ ei_raw,
    const float* __restrict__ W2,       // [64, 64]
    const float* __restrict__ b2,       // [64]
    float* __restrict__ out,            // [n, 64]
    int n, int E) {
    extern __shared__ float smem[];
    float* Hs  = smem;                       // TILE_E * H_STRIDE
    float* W2s = smem + TILE_E * H_STRIDE;   // 64 * 64
    float* b2s = W2s + 64 * 64;              // 64
    int*   dsts = (int*)(b2s + 64);          // TILE_E

    const int tid = threadIdx.x;
    for (int i = tid; i < 64 * 64; i += 256) W2s[i] = W2[i];
    if (tid < 64) b2s[tid] = b2[tid];

    const int is64 = g_is64;
    const long long* ei64 = (const long long*)ei_raw;
    const int*       ei32 = (const int*)ei_raw;
    const int total = E + n;
    const int base = blockIdx.x * TILE_E;

    // ---------------- Stage 1: gather + relu into Hs ----------------
    {
        const int c  = tid & 15;   // float4 chunk of the 64-wide row
        const int es = tid >> 4;   // edge sub-index 0..15
#pragma unroll
        for (int j = 0; j < TILE_E / 16; j++) {
            int el = j * 16 + es;
            int eg_ = base + el;
            float4 h;
            if (eg_ < total) {
                long long s, d;
                if (eg_ < E) {
                    if (is64) { s = ei64[eg_]; d = ei64[E + eg_]; }
                    else      { s = ei32[eg_]; d = ei32[E + eg_]; }
                } else { s = eg_ - E; d = s; }
                float4 u = *(const float4*)&g_U[s * 64 + c * 4];
                float4 p = *(const float4*)&g_P[d * 64 + c * 4];
                h.x = fmaxf(u.x - p.x, 0.0f);
                h.y = fmaxf(u.y - p.y, 0.0f);
                h.z = fmaxf(u.z - p.z, 0.0f);
                h.w = fmaxf(u.w - p.w, 0.0f);
                if (c == 0) dsts[el] = (int)d;
            } else {
                h = make_float4(0.0f, 0.0f, 0.0f, 0.0f);
                if (c == 0) dsts[el] = -1;
            }
            *(float4*)&Hs[el * H_STRIDE + c * 4] = h;
        }
    }
    __syncthreads();

    // ---------------- Stage 2: GEMM ----------------
    const int eg = tid & 15;
    const int kb = (tid >> 4) * 4;

    unsigned long long acc[8][2];
#pragma unroll
    for (int i = 0; i < 8; i++) { acc[i][0] = 0ull; acc[i][1] = 0ull; }

#pragma unroll
    for (int m4 = 0; m4 < 16; m4++) {
        // W2 rows m4*4 .. m4*4+3, columns kb..kb+3, as f32x2 pairs
        ulonglong2 w0 = *(const ulonglong2*)&W2s[(m4 * 4 + 0) * 64 + kb];
        ulonglong2 w1 = *(const ulonglong2*)&W2s[(m4 * 4 + 1) * 64 + kb];
        ulonglong2 w2v = *(const ulonglong2*)&W2s[(m4 * 4 + 2) * 64 + kb];
        ulonglong2 w3 = *(const ulonglong2*)&W2s[(m4 * 4 + 3) * 64 + kb];
#pragma unroll
        for (int i = 0; i < 8; i++) {
            const float4 hv = *(const float4*)&Hs[(eg + 16 * i) * H_STRIDE + m4 * 4];
            unsigned long long hb;
            hb = packdup(hv.x); ffma2(acc[i][0], hb, w0.x);  ffma2(acc[i][1], hb, w0.y);
            hb = packdup(hv.y); ffma2(acc[i][0], hb, w1.x);  ffma2(acc[i][1], hb, w1.y);
            hb = packdup(hv.z); ffma2(acc[i][0], hb, w2v.x); ffma2(acc[i][1], hb, w2v.y);
            hb = packdup(hv.w); ffma2(acc[i][0], hb, w3.x);  ffma2(acc[i][1], hb, w3.y);
        }
    }

    // ---------------- Stage 3: scatter-max ----------------
    const float bb0 = b2s[kb + 0];
    const float bb1 = b2s[kb + 1];
    const float bb2 = b2s[kb + 2];
    const float bb3 = b2s[kb + 3];
#pragma unroll
    for (int i = 0; i < 8; i++) {
        int d = dsts[eg + 16 * i];
        if (d < 0) continue;
        float v0, v1, v2, v3;
        unpack2(acc[i][0], v0, v1);
        unpack2(acc[i][1], v2, v3);
        v0 += bb0; v1 += bb1; v2 += bb2; v3 += bb3;
        float* o = out + (long long)d * 64 + kb;
        float4 cur = *(const float4*)o;
        if (v0 > cur.x) atomicMaxF(o + 0, v0);
        if (v1 > cur.y) atomicMaxF(o + 1, v1);
        if (v2 > cur.z) atomicMaxF(o + 2, v2);
        if (v3 > cur.w) atomicMaxF(o + 3, v3);
    }
}

// ---------------------------------------------------------------------------
// Launch
// ---------------------------------------------------------------------------
extern "C" void kernel_launch(void* const* d_in, const int* in_sizes, int n_in,
                              void* d_out, int out_size) {
    const float* x   = (const float*)d_in[0];    // [n, 32]
    const float* pos = (const float*)d_in[1];    // [n, 3]
    const void*  ei  = d_in[2];                  // [2, E] int64 or int32
    const float* W1  = (const float*)d_in[3];    // [35, 64]
    const float* b1  = (const float*)d_in[4];    // [64]
    const float* W2  = (const float*)d_in[5];    // [64, 64]
    const float* b2  = (const float*)d_in[6];    // [64]
    float*       out = (float*)d_out;            // [n, 64]

    int n = in_sizes[0] / D_FEAT;
    int E = in_sizes[2] / 2;

    const int smemBytes = (TILE_E * H_STRIDE + 64 * 64 + 64) * 4 + TILE_E * 4;
    static int attrDone = 0;
    (void)attrDone;
    cudaFuncSetAttribute(edge_kernel, cudaFuncAttributeMaxDynamicSharedMemorySize,
                         smemBytes);

    // 0) detect edge_index dtype (int64 vs int32)
    detect_kernel<<<1, 256>>>((const long long*)ei, E, n);

    // 1) per-node precompute
    {
        int threads = 256;
        int blocks = (n * 64 + threads - 1) / threads;
        precompute_kernel<<<blocks, threads>>>(x, pos, W1, b1, n);
    }
    // 2) init output
    {
        int threads = 256;
        int blocks = (n * 64 + threads - 1) / threads;
        init_out_kernel<<<blocks, threads>>>(out, n * 64);
    }
    // 3) edge kernel: 128-edge tiles
    {
        int total = E + n;
        int blocks = (total + TILE_E - 1) / TILE_E;
        edge_kernel<<<blocks, 256, smemBytes>>>(ei, W2, b2, out, n, E);
    }
}

// round 4
// speedup vs baseline: 1.7258x; 1.3386x over previous
#include <cuda_runtime.h>
#include <cuda_bf16.h>
#include <float.h>

// Problem constants (fixed by the dataset)
#define MAX_NODES 100000
#define D_FEAT 32
#define D_HID 64
#define D_OUT 64
#define TILE_E 128
#define H_STRIDE 68   // floats per H row (64 + pad, 16B-aligned)

// Scratch: per-node precomputed terms.
// U[j] = x_j @ W1[:32] + pos_j @ W1[32:35] + b1   (N x 64)
// P[i] = pos_i @ W1[32:35]                        (N x 64)
// Per-edge preactivation = U[src] - P[dst].
__device__ float g_U[MAX_NODES * D_HID];
__device__ float g_P[MAX_NODES * D_HID];

// 1 if edge_index is genuinely int64, 0 if int32 on disk.
__device__ int g_is64;

// ---------------------------------------------------------------------------
// packed fp32x2 helpers (sm_100+ PTX; bit-exact pair of fp32 FMAs)
// ---------------------------------------------------------------------------
__device__ __forceinline__ void ffma2(unsigned long long& d,
                                      unsigned long long a,
                                      unsigned long long b) {
    asm("fma.rn.f32x2 %0, %1, %2, %0;" : "+l"(d) : "l"(a), "l"(b));
}
__device__ __forceinline__ unsigned long long packdup(float x) {
    unsigned long long r;
    asm("mov.b64 %0, {%1, %1};" : "=l"(r) : "f"(x));
    return r;
}
__device__ __forceinline__ void unpack2(unsigned long long v, float& lo, float& hi) {
    asm("mov.b64 {%0, %1}, %2;" : "=f"(lo), "=f"(hi) : "l"(v));
}

// ---------------------------------------------------------------------------
// Kernel 0: detect edge_index element width (int64 vs int32).
// ---------------------------------------------------------------------------
__global__ void detect_kernel(const long long* __restrict__ ei64, int E, int n) {
    __shared__ int bad;
    if (threadIdx.x == 0) bad = 0;
    __syncthreads();
    int samples = min(4096, E);
    for (int i = threadIdx.x; i < samples; i += blockDim.x) {
        long long v = ei64[i];
        if (v < 0 || v >= (long long)n) atomicOr(&bad, 1);
    }
    __syncthreads();
    if (threadIdx.x == 0) g_is64 = bad ? 0 : 1;
}

// ---------------------------------------------------------------------------
// Kernel 1: per-node precompute of U and P. One thread per (node, hid).
// ---------------------------------------------------------------------------
__global__ void precompute_kernel(const float* __restrict__ x,
                                  const float* __restrict__ pos,
                                  const float* __restrict__ W1,
                                  const float* __restrict__ b1,
                                  int n) {
    __shared__ float W1s[35 * 64];
    __shared__ float b1s[64];
    for (int i = threadIdx.x; i < 35 * 64; i += blockDim.x) W1s[i] = W1[i];
    if (threadIdx.x < 64) b1s[threadIdx.x] = b1[threadIdx.x];
    __syncthreads();

    int gid = blockIdx.x * blockDim.x + threadIdx.x;
    int node = gid >> 6;
    int k = gid & 63;
    if (node >= n) return;

    const float* xr = x + node * D_FEAT;
    float acc = b1s[k];
#pragma unroll
    for (int f = 0; f < D_FEAT; f++) {
        acc = fmaf(xr[f], W1s[f * 64 + k], acc);
    }
    float px = pos[node * 3 + 0];
    float py = pos[node * 3 + 1];
    float pz = pos[node * 3 + 2];
    float pp = px * W1s[32 * 64 + k];
    pp = fmaf(py, W1s[33 * 64 + k], pp);
    pp = fmaf(pz, W1s[34 * 64 + k], pp);

    g_U[node * 64 + k] = acc + pp;
    g_P[node * 64 + k] = pp;
}

// ---------------------------------------------------------------------------
// Kernel 2: init output to -FLT_MAX.
// ---------------------------------------------------------------------------
__global__ void init_out_kernel(float* __restrict__ out, int total) {
    int i = blockIdx.x * blockDim.x + threadIdx.x;
    if (i < total) out[i] = -FLT_MAX;
}

// ---------------------------------------------------------------------------
// float atomicMax via int/uint bit tricks
// ---------------------------------------------------------------------------
__device__ __forceinline__ void atomicMaxF(float* addr, float v) {
    if (v >= 0.0f) {
        atomicMax((int*)addr, __float_as_int(v));
    } else {
        atomicMin((unsigned int*)addr, __float_as_uint(v));
    }
}

// ---------------------------------------------------------------------------
// Kernel 3: edge kernel, register-tiled, broadcast-friendly layout.
// Tile = 128 edges x 64 outputs per block (256 threads).
// Thread tile = 4 edges x 8 outputs.
//   cg = tid & 7   -> cols {cg*4..cg*4+3} and {32+cg*4..32+cg*4+3}
//   e0 = tid >> 3  -> edges e0, e0+32, e0+64, e0+96
// Within a warp: 4 distinct H rows (8-way broadcast, 1 smem phase) and
// w chunks at word offsets cg*4 covering banks 0..31 exactly (1 phase).
// ---------------------------------------------------------------------------
__global__ void __launch_bounds__(256, 3) edge_kernel(
    const void* __restrict__ ei_raw,
    const float* __restrict__ W2,       // [64, 64]
    const float* __restrict__ b2,       // [64]
    float* __restrict__ out,            // [n, 64]
    int n, int E) {
    extern __shared__ float smem[];
    float* Hs  = smem;                       // TILE_E * H_STRIDE
    float* W2s = smem + TILE_E * H_STRIDE;   // 64 * 64
    float* b2s = W2s + 64 * 64;              // 64
    int*   dsts = (int*)(b2s + 64);          // TILE_E

    const int tid = threadIdx.x;
    for (int i = tid; i < 64 * 64; i += 256) W2s[i] = W2[i];
    if (tid < 64) b2s[tid] = b2[tid];

    const int is64 = g_is64;
    const long long* ei64 = (const long long*)ei_raw;
    const int*       ei32 = (const int*)ei_raw;
    const int total = E + n;
    const int base = blockIdx.x * TILE_E;

    // ---------------- Stage 1: gather + relu into Hs ----------------
    {
        const int c  = tid & 15;   // float4 chunk of the 64-wide row
        const int es = tid >> 4;   // edge sub-index 0..15
#pragma unroll
        for (int j = 0; j < TILE_E / 16; j++) {
            int el = j * 16 + es;
            int eg_ = base + el;
            float4 h;
            if (eg_ < total) {
                long long s, d;
                if (eg_ < E) {
                    if (is64) { s = ei64[eg_]; d = ei64[E + eg_]; }
                    else      { s = ei32[eg_]; d = ei32[E + eg_]; }
                } else { s = eg_ - E; d = s; }
                float4 u = *(const float4*)&g_U[s * 64 + c * 4];
                float4 p = *(const float4*)&g_P[d * 64 + c * 4];
                h.x = fmaxf(u.x - p.x, 0.0f);
                h.y = fmaxf(u.y - p.y, 0.0f);
                h.z = fmaxf(u.z - p.z, 0.0f);
                h.w = fmaxf(u.w - p.w, 0.0f);
                if (c == 0) dsts[el] = (int)d;
            } else {
                h = make_float4(0.0f, 0.0f, 0.0f, 0.0f);
                if (c == 0) dsts[el] = -1;
            }
            *(float4*)&Hs[el * H_STRIDE + c * 4] = h;
        }
    }
    __syncthreads();

    // ---------------- Stage 2: GEMM ----------------
    const int cg = tid & 7;
    const int e0 = tid >> 3;        // 0..31
    const int kb1 = cg * 4;         // cols kb1..kb1+3
    const int kb2 = 32 + cg * 4;    // cols kb2..kb2+3

    // acc[i][0..1] -> cols kb1..kb1+3; acc[i][2..3] -> cols kb2..kb2+3
    unsigned long long acc[4][4];
#pragma unroll
    for (int i = 0; i < 4; i++)
#pragma unroll
        for (int j = 0; j < 4; j++) acc[i][j] = 0ull;

#pragma unroll
    for (int m4 = 0; m4 < 16; m4++) {
        float h0[4], h1[4], h2[4], h3[4];
        {
            float4 t;
            t = *(const float4*)&Hs[(e0 +  0) * H_STRIDE + m4 * 4];
            h0[0] = t.x; h0[1] = t.y; h0[2] = t.z; h0[3] = t.w;
            t = *(const float4*)&Hs[(e0 + 32) * H_STRIDE + m4 * 4];
            h1[0] = t.x; h1[1] = t.y; h1[2] = t.z; h1[3] = t.w;
            t = *(const float4*)&Hs[(e0 + 64) * H_STRIDE + m4 * 4];
            h2[0] = t.x; h2[1] = t.y; h2[2] = t.z; h2[3] = t.w;
            t = *(const float4*)&Hs[(e0 + 96) * H_STRIDE + m4 * 4];
            h3[0] = t.x; h3[1] = t.y; h3[2] = t.z; h3[3] = t.w;
        }
#pragma unroll
        for (int mm = 0; mm < 4; mm++) {
            const int m = m4 * 4 + mm;
            ulonglong2 wA = *(const ulonglong2*)&W2s[m * 64 + kb1];
            ulonglong2 wB = *(const ulonglong2*)&W2s[m * 64 + kb2];
            unsigned long long hb;
            hb = packdup(h0[mm]);
            ffma2(acc[0][0], hb, wA.x); ffma2(acc[0][1], hb, wA.y);
            ffma2(acc[0][2], hb, wB.x); ffma2(acc[0][3], hb, wB.y);
            hb = packdup(h1[mm]);
            ffma2(acc[1][0], hb, wA.x); ffma2(acc[1][1], hb, wA.y);
            ffma2(acc[1][2], hb, wB.x); ffma2(acc[1][3], hb, wB.y);
            hb = packdup(h2[mm]);
            ffma2(acc[2][0], hb, wA.x); ffma2(acc[2][1], hb, wA.y);
            ffma2(acc[2][2], hb, wB.x); ffma2(acc[2][3], hb, wB.y);
            hb = packdup(h3[mm]);
            ffma2(acc[3][0], hb, wA.x); ffma2(acc[3][1], hb, wA.y);
            ffma2(acc[3][2], hb, wB.x); ffma2(acc[3][3], hb, wB.y);
        }
    }

    // ---------------- Stage 3: scatter-max ----------------
    const float4 bbA = *(const float4*)&b2s[kb1];
    const float4 bbB = *(const float4*)&b2s[kb2];
#pragma unroll
    for (int i = 0; i < 4; i++) {
        int d = dsts[e0 + 32 * i];
        if (d < 0) continue;
        float v0, v1, v2, v3, v4, v5, v6, v7;
        unpack2(acc[i][0], v0, v1);
        unpack2(acc[i][1], v2, v3);
        unpack2(acc[i][2], v4, v5);
        unpack2(acc[i][3], v6, v7);
        v0 += bbA.x; v1 += bbA.y; v2 += bbA.z; v3 += bbA.w;
        v4 += bbB.x; v5 += bbB.y; v6 += bbB.z; v7 += bbB.w;
        float* oA = out + (long long)d * 64 + kb1;
        float* oB = out + (long long)d * 64 + kb2;
        float4 curA = *(const float4*)oA;
        float4 curB = *(const float4*)oB;
        if (v0 > curA.x) atomicMaxF(oA + 0, v0);
        if (v1 > curA.y) atomicMaxF(oA + 1, v1);
        if (v2 > curA.z) atomicMaxF(oA + 2, v2);
        if (v3 > curA.w) atomicMaxF(oA + 3, v3);
        if (v4 > curB.x) atomicMaxF(oB + 0, v4);
        if (v5 > curB.y) atomicMaxF(oB + 1, v5);
        if (v6 > curB.z) atomicMaxF(oB + 2, v6);
        if (v7 > curB.w) atomicMaxF(oB + 3, v7);
    }
}

// ---------------------------------------------------------------------------
// Launch
// ---------------------------------------------------------------------------
extern "C" void kernel_launch(void* const* d_in, const int* in_sizes, int n_in,
                              void* d_out, int out_size) {
    const float* x   = (const float*)d_in[0];    // [n, 32]
    const float* pos = (const float*)d_in[1];    // [n, 3]
    const void*  ei  = d_in[2];                  // [2, E] int64 or int32
    const float* W1  = (const float*)d_in[3];    // [35, 64]
    const float* b1  = (const float*)d_in[4];    // [64]
    const float* W2  = (const float*)d_in[5];    // [64, 64]
    const float* b2  = (const float*)d_in[6];    // [64]
    float*       out = (float*)d_out;            // [n, 64]

    int n = in_sizes[0] / D_FEAT;
    int E = in_sizes[2] / 2;

    const int smemBytes = (TILE_E * H_STRIDE + 64 * 64 + 64) * 4 + TILE_E * 4;
    cudaFuncSetAttribute(edge_kernel, cudaFuncAttributeMaxDynamicSharedMemorySize,
                         smemBytes);

    // 0) detect edge_index dtype (int64 vs int32)
    detect_kernel<<<1, 256>>>((const long long*)ei, E, n);

    // 1) per-node precompute
    {
        int threads = 256;
        int blocks = (n * 64 + threads - 1) / threads;
        precompute_kernel<<<blocks, threads>>>(x, pos, W1, b1, n);
    }
    // 2) init output
    {
        int threads = 256;
        int blocks = (n * 64 + threads - 1) / threads;
        init_out_kernel<<<blocks, threads>>>(out, n * 64);
    }
    // 3) edge kernel: 128-edge tiles
    {
        int total = E + n;
        int blocks = (total + TILE_E - 1) / TILE_E;
        edge_kernel<<<blocks, 256, smemBytes>>>(ei, W2, b2, out, n, E);
    }
}